// round 3
// baseline (speedup 1.0000x reference)
#include <cuda_runtime.h>
#include <cstdint>

// WordEmbedding: out[row, :] = W[ids[row], :]
//   W:   [50257, 1024] float32   (51,463,168 elements)
//   ids: [16, 2048]              (32,768 elements) -- harness delivers int32
//   out: [32768, 1024] float32
//
// HBM-bound gather. One CTA per row; 256 threads x float4 = 4KB row.

#define DIM 1024
#define VEC_PER_ROW (DIM / 4)   // 256 float4 per row

__global__ __launch_bounds__(256, 8)
void WordEmbedding_43181601194151_kernel(const float4* __restrict__ w,
                                         const int* __restrict__ ids,
                                         float4* __restrict__ out)
{
    const int row = blockIdx.x;
    const int id = __ldg(&ids[row]);

    const float4* __restrict__ src = w + (size_t)id * VEC_PER_ROW;
    float4* __restrict__ dst = out + (size_t)row * VEC_PER_ROW;

    dst[threadIdx.x] = __ldg(&src[threadIdx.x]);
}

extern "C" void kernel_launch(void* const* d_in, const int* in_sizes, int n_in,
                              void* d_out, int out_size)
{
    // Select inputs by size: the weight matrix is by far the larger tensor.
    int w_idx = 0, id_idx = 1;
    if (n_in >= 2 && in_sizes[1] > in_sizes[0]) { w_idx = 1; id_idx = 0; }

    const float4* w   = (const float4*)d_in[w_idx];
    const int*    ids = (const int*)d_in[id_idx];
    float4*       out = (float4*)d_out;

    const int n_rows = out_size / DIM;   // 32768

    WordEmbedding_43181601194151_kernel<<<n_rows, 256>>>(w, ids, out);
}

// round 4
// speedup vs baseline: 1.1956x; 1.1956x over previous
#include <cuda_runtime.h>
#include <cstdint>

// WordEmbedding: out[row, :] = W[ids[row], :]
//   W:   [50257, 1024] float32   (51,463,168 elements)
//   ids: [32768] int32 (harness delivers int32)
//   out: [32768, 1024] float32
//
// HBM-bound gather. 8 rows per CTA, front-batched loads for MLP=8/thread.
// Streaming stores keep L2 reserved for the gathered weight rows.

#define DIM 1024
#define VEC_PER_ROW (DIM / 4)   // 256 float4 per row
#define ROWS_PER_CTA 8

__global__ __launch_bounds__(256, 4)
void WordEmbedding_43181601194151_kernel(const float4* __restrict__ w,
                                         const int* __restrict__ ids,
                                         float4* __restrict__ out)
{
    const int base_row = blockIdx.x * ROWS_PER_CTA;
    const int t = threadIdx.x;

    int id[ROWS_PER_CTA];
#pragma unroll
    for (int r = 0; r < ROWS_PER_CTA; r++)
        id[r] = __ldg(&ids[base_row + r]);

    // Front-batch all 8 gathered loads (independent -> 8 outstanding per thread)
    float4 v[ROWS_PER_CTA];
#pragma unroll
    for (int r = 0; r < ROWS_PER_CTA; r++)
        v[r] = __ldg(&w[(size_t)id[r] * VEC_PER_ROW + t]);

    // Streaming stores: don't let the 128MB output stream evict weight rows from L2
#pragma unroll
    for (int r = 0; r < ROWS_PER_CTA; r++)
        __stcs(&out[(size_t)(base_row + r) * VEC_PER_ROW + t], v[r]);
}

extern "C" void kernel_launch(void* const* d_in, const int* in_sizes, int n_in,
                              void* d_out, int out_size)
{
    // Select inputs by size: the weight matrix is by far the larger tensor.
    int w_idx = 0, id_idx = 1;
    if (n_in >= 2 && in_sizes[1] > in_sizes[0]) { w_idx = 1; id_idx = 0; }

    const float4* w   = (const float4*)d_in[w_idx];
    const int*    ids = (const int*)d_in[id_idx];
    float4*       out = (float4*)d_out;

    const int n_rows = out_size / DIM;               // 32768
    const int n_blocks = n_rows / ROWS_PER_CTA;      // 4096

    WordEmbedding_43181601194151_kernel<<<n_blocks, 256>>>(w, ids, out);
}